// round 3
// baseline (speedup 1.0000x reference)
#include <cuda_runtime.h>

#define NDEV 63
#define NN   64
#define DDIM 14
#define SDIM 3
#define HID  64
#define HH   128
#define FULL 0xffffffffu

__global__ __launch_bounds__(256) void pgcn_kernel(
    const float* __restrict__ device_obs,
    const float* __restrict__ server_obs,
    const float* __restrict__ adjacency,
    const float* __restrict__ W_dev, const float* __restrict__ b_dev,
    const float* __restrict__ W_srv, const float* __restrict__ b_srv,
    const float* __restrict__ W1, const float* __restrict__ b1,
    const float* __restrict__ W2, const float* __restrict__ b2,
    const float* __restrict__ W3, const float* __restrict__ b3,
    const float* __restrict__ Wf1, const float* __restrict__ bf1,
    const float* __restrict__ Wf2, const float* __restrict__ bf2,
    float* __restrict__ out)
{
    // ping-pong node-feature buffers: [64 nodes][32 float2] (h = 2*lane, 2*lane+1)
    __shared__ float2 bufA[NN * 32];
    __shared__ float2 bufB[NN * 32];
    __shared__ float  tail[2 * HID];   // [mean(64) | server_hidden(64)]

    const int b    = blockIdx.x;
    const int tid  = threadIdx.x;
    const int w    = tid >> 5;
    const int lane = tid & 31;

    // ---------------- Phase 1: adjacency -> bitmasks + dinv (warp-uniform regs)
    unsigned mlo[8], mhi[8];
    float dinv[8];
    const float* adj = adjacency + (size_t)b * NN * NN;
    #pragma unroll
    for (int i = 0; i < 8; i++) {
        const int n = w * 8 + i;
        const float a0 = adj[n * 64 + lane];
        const float a1 = adj[n * 64 + 32 + lane];
        mlo[i] = __ballot_sync(FULL, a0 > 0.5f);
        mhi[i] = __ballot_sync(FULL, a1 > 0.5f);
        const int deg = __popc(mlo[i]) + __popc(mhi[i]);   // >= 1 (self loop)
        dinv[i] = rsqrtf((float)deg);
    }

    // ---------------- Phase 2: embeddings -> bufA (pre-scaled by dinv[m])
    {
        const float2 bd = __ldg((const float2*)&b_dev[2 * lane]);
        #pragma unroll
        for (int i = 0; i < 8; i++) {
            const int n = w * 8 + i;
            float2 acc;
            if (n < NDEV) {
                acc = bd;
                const float* obs = device_obs + ((size_t)b * NDEV + n) * DDIM;
                #pragma unroll
                for (int d = 0; d < DDIM; d++) {
                    const float  o  = __ldg(&obs[d]);
                    const float2 wv = __ldg((const float2*)&W_dev[d * HID + 2 * lane]);
                    acc.x += o * wv.x; acc.y += o * wv.y;
                }
            } else {  // n == 63 : server node
                acc = __ldg((const float2*)&b_srv[2 * lane]);
                const float* obs = server_obs + (size_t)b * SDIM;
                #pragma unroll
                for (int d = 0; d < SDIM; d++) {
                    const float  o  = __ldg(&obs[d]);
                    const float2 wv = __ldg((const float2*)&W_srv[d * HID + 2 * lane]);
                    acc.x += o * wv.x; acc.y += o * wv.y;
                }
            }
            acc.x = fmaxf(acc.x, 0.f) * dinv[i];
            acc.y = fmaxf(acc.y, 0.f) * dinv[i];
            bufA[n * 32 + lane] = acc;
        }
    }

    float2* cur = bufA;
    float2* nxt = bufB;
    const float* Ws[3] = {W1, W2, W3};
    const float* bs[3] = {b1, b2, b3};

    // ---------------- Phase 3: three GCN layers
    #pragma unroll
    for (int L = 0; L < 3; L++) {
        __syncthreads();  // all writers of `cur` done; all readers of `nxt` done

        // Sparse aggregation (binary adjacency): y kept in registers
        float ax[8], ay[8];
        #pragma unroll
        for (int i = 0; i < 8; i++) {
            unsigned lo = mlo[i], hi = mhi[i];
            float sx = 0.f, sy = 0.f;
            while (lo) { const int m = __ffs(lo) - 1;      lo &= lo - 1;
                         const float2 v = cur[m * 32 + lane]; sx += v.x; sy += v.y; }
            while (hi) { const int m = __ffs(hi) - 1 + 32; hi &= hi - 1;
                         const float2 v = cur[m * 32 + lane]; sx += v.x; sy += v.y; }
            ax[i] = sx * dinv[i];
            ay[i] = sy * dinv[i];
        }

        // Dense W matmul: h_out[n][k] = relu(sum_h y[n][h] * W[h][k] + b[k])
        // y broadcast across the warp via shfl (lane l holds h=2l, 2l+1)
        const float* W = Ws[L];
        const float2 bias = __ldg((const float2*)&bs[L][2 * lane]);
        float2 acc[8];
        #pragma unroll
        for (int i = 0; i < 8; i++) acc[i] = bias;

        for (int h2 = 0; h2 < 32; h2++) {
            const float2 w0 = __ldg((const float2*)&W[(2 * h2    ) * HID + 2 * lane]);
            const float2 w1 = __ldg((const float2*)&W[(2 * h2 + 1) * HID + 2 * lane]);
            #pragma unroll
            for (int i = 0; i < 8; i++) {
                const float y0 = __shfl_sync(FULL, ax[i], h2);
                const float y1 = __shfl_sync(FULL, ay[i], h2);
                acc[i].x += y0 * w0.x; acc[i].x += y1 * w1.x;
                acc[i].y += y0 * w0.y; acc[i].y += y1 * w1.y;
            }
        }

        // Store: layers 0,1 pre-scale by dinv for next aggregation; layer 2 raw.
        #pragma unroll
        for (int i = 0; i < 8; i++) {
            const int n = w * 8 + i;
            float2 v;
            v.x = fmaxf(acc[i].x, 0.f);
            v.y = fmaxf(acc[i].y, 0.f);
            if (L < 2) { v.x *= dinv[i]; v.y *= dinv[i]; }
            nxt[n * 32 + lane] = v;
        }
        { float2* t = cur; cur = nxt; nxt = t; }
    }

    __syncthreads();

    // ---------------- Phase 4: dev mean + server hidden -> tail
    const float* hb = (const float*)cur;
    if (tid < 64) {
        float s = 0.f;
        for (int n = 0; n < NDEV; n++) s += hb[n * 64 + tid];
        tail[tid]      = s * (1.0f / 63.0f);
        tail[64 + tid] = hb[63 * 64 + tid];
    }
    __syncthreads();

    // ---------------- Phase 5: head
    // z[n][j] = relu( sum_{i<64} h[n][i]*Wf1[i][j]  +  common[j] + bf1[j] )
    // common[j] = sum_{t<128} tail[t]*Wf1[64+t][j]   (node-invariant!)
    const float4 bz = __ldg((const float4*)&bf1[4 * lane]);
    float4 za[8];
    #pragma unroll
    for (int i = 0; i < 8; i++) za[i] = bz;

    for (int t = 0; t < 64; t++) {
        const float4 wf = __ldg((const float4*)&Wf1[t * HH + 4 * lane]);
        #pragma unroll
        for (int i = 0; i < 8; i++) {
            const float c = hb[(w * 8 + i) * 64 + t];
            za[i].x += c * wf.x; za[i].y += c * wf.y;
            za[i].z += c * wf.z; za[i].w += c * wf.w;
        }
    }

    float4 zc = make_float4(0.f, 0.f, 0.f, 0.f);
    for (int t = 0; t < 128; t++) {
        const float4 wf = __ldg((const float4*)&Wf1[(64 + t) * HH + 4 * lane]);
        const float  c  = tail[t];
        zc.x += c * wf.x; zc.y += c * wf.y; zc.z += c * wf.z; zc.w += c * wf.w;
    }

    const float4 wf2v = __ldg((const float4*)&Wf2[4 * lane]);
    const float  bf2v = __ldg(bf2);

    #pragma unroll
    for (int i = 0; i < 8; i++) {
        const int n = w * 8 + i;
        if (n == 63) continue;            // warp-uniform (only warp 7, i==7)
        const float zx = fmaxf(za[i].x + zc.x, 0.f);
        const float zy = fmaxf(za[i].y + zc.y, 0.f);
        const float zz = fmaxf(za[i].z + zc.z, 0.f);
        const float zw = fmaxf(za[i].w + zc.w, 0.f);
        float p = zx * wf2v.x + zy * wf2v.y + zz * wf2v.z + zw * wf2v.w;
        p += __shfl_xor_sync(FULL, p, 16);
        p += __shfl_xor_sync(FULL, p, 8);
        p += __shfl_xor_sync(FULL, p, 4);
        p += __shfl_xor_sync(FULL, p, 2);
        p += __shfl_xor_sync(FULL, p, 1);
        if (lane == 0) out[(size_t)b * NDEV + n] = p + bf2v;
    }
}

extern "C" void kernel_launch(void* const* d_in, const int* in_sizes, int n_in,
                              void* d_out, int out_size)
{
    const float* device_obs = (const float*)d_in[0];
    const float* server_obs = (const float*)d_in[1];
    const float* adjacency  = (const float*)d_in[2];
    const float* W_dev = (const float*)d_in[3];
    const float* b_dev = (const float*)d_in[4];
    const float* W_srv = (const float*)d_in[5];
    const float* b_srv = (const float*)d_in[6];
    const float* W1 = (const float*)d_in[7];
    const float* b1 = (const float*)d_in[8];
    const float* W2 = (const float*)d_in[9];
    const float* b2 = (const float*)d_in[10];
    const float* W3 = (const float*)d_in[11];
    const float* b3 = (const float*)d_in[12];
    const float* Wf1 = (const float*)d_in[13];
    const float* bf1 = (const float*)d_in[14];
    const float* Wf2 = (const float*)d_in[15];
    const float* bf2 = (const float*)d_in[16];

    const int B = in_sizes[1] / SDIM;   // server_obs is (B, 3)

    pgcn_kernel<<<B, 256>>>(device_obs, server_obs, adjacency,
                            W_dev, b_dev, W_srv, b_srv,
                            W1, b1, W2, b2, W3, b3,
                            Wf1, bf1, Wf2, bf2,
                            (float*)d_out);
}

// round 4
// speedup vs baseline: 1.2759x; 1.2759x over previous
#include <cuda_runtime.h>

#define NDEV 63
#define NN   64
#define DDIM 14
#define SDIM 3
#define HID  64
#define HH   128
#define FULL 0xffffffffu
#define PAD  66   // padded row stride (floats) for transposed buffers

typedef unsigned long long u64;

__device__ __forceinline__ u64 pk2(float x, float y) {
    u64 r; asm("mov.b64 %0,{%1,%2};" : "=l"(r) : "f"(x), "f"(y)); return r;
}
__device__ __forceinline__ u64 dup2(float x) { return pk2(x, x); }
__device__ __forceinline__ void up2(u64 v, float& x, float& y) {
    asm("mov.b64 {%0,%1},%2;" : "=f"(x), "=f"(y) : "l"(v));
}
__device__ __forceinline__ u64 fma2(u64 a, u64 b, u64 c) {
    u64 d; asm("fma.rn.f32x2 %0,%1,%2,%3;" : "=l"(d) : "l"(a), "l"(b), "l"(c)); return d;
}
__device__ __forceinline__ u64 add2(u64 a, u64 b) {
    u64 d; asm("add.rn.f32x2 %0,%1,%2;" : "=l"(d) : "l"(a), "l"(b)); return d;
}
__device__ __forceinline__ u64 mul2(u64 a, u64 b) {
    u64 d; asm("mul.rn.f32x2 %0,%1,%2;" : "=l"(d) : "l"(a), "l"(b)); return d;
}

__global__ __launch_bounds__(256, 4) void pgcn_kernel(
    const float* __restrict__ device_obs,
    const float* __restrict__ server_obs,
    const float* __restrict__ adjacency,
    const float* __restrict__ W_dev, const float* __restrict__ b_dev,
    const float* __restrict__ W_srv, const float* __restrict__ b_srv,
    const float* __restrict__ W1, const float* __restrict__ b1,
    const float* __restrict__ W2, const float* __restrict__ b2,
    const float* __restrict__ W3, const float* __restrict__ b3,
    const float* __restrict__ Wf1, const float* __restrict__ bf1,
    const float* __restrict__ Wf2, const float* __restrict__ bf2,
    float* __restrict__ out)
{
    // xb: node-major features [n][h] (stride PAD). After layer-2 matmul it is
    //     reused as h3T [k][n] (stride PAD).
    // yb: aggregated features, transposed [k][n] (stride PAD).
    __shared__ __align__(16) float xb[NN * PAD];
    __shared__ __align__(16) float yb[NN * PAD];
    __shared__ __align__(16) float dinvS[NN];
    __shared__ __align__(16) float tailS[2 * HID];   // [mean(64) | server(64)]
    __shared__ __align__(16) float comS[HH];         // common head term + bf1
    __shared__ __align__(16) float part[4 * HH];     // partials; reused as head scratch

    const int b    = blockIdx.x;
    const int tid  = threadIdx.x;
    const int w    = tid >> 5;
    const int lane = tid & 31;

    // ---------------- Phase 1: adjacency -> warp-uniform bitmasks + dinv
    unsigned mlo[8], mhi[8];
    float dinv[8];
    {
        const float* adj = adjacency + (size_t)b * NN * NN;
        #pragma unroll
        for (int i = 0; i < 8; i++) {
            const int n = w * 8 + i;
            const float a0 = adj[n * 64 + lane];
            const float a1 = adj[n * 64 + 32 + lane];
            mlo[i] = __ballot_sync(FULL, a0 > 0.5f);
            mhi[i] = __ballot_sync(FULL, a1 > 0.5f);
            const int deg = __popc(mlo[i]) + __popc(mhi[i]);  // >= 1 (self loop)
            dinv[i] = rsqrtf((float)deg);
            if (lane == 0) dinvS[n] = dinv[i];
        }
    }

    // ---------------- Phase 2: embeddings -> xb[n][h] (relu'd, pre-scaled by dinv)
    {
        u64 acc[8];
        const float2 bdv = __ldg((const float2*)&b_dev[2 * lane]);
        const u64 bd = pk2(bdv.x, bdv.y);
        #pragma unroll
        for (int i = 0; i < 8; i++) acc[i] = bd;
        if (w == 7) {
            const float2 bsv = __ldg((const float2*)&b_srv[2 * lane]);
            acc[7] = pk2(bsv.x, bsv.y);
        }
        const float* obsb = device_obs + (size_t)b * NDEV * DDIM;
        #pragma unroll
        for (int d = 0; d < DDIM; d++) {
            const float2 wv2 = __ldg((const float2*)&W_dev[d * HID + 2 * lane]);
            const u64 wv = pk2(wv2.x, wv2.y);
            #pragma unroll
            for (int i = 0; i < 8; i++) {
                const int n = w * 8 + i;
                if (n < NDEV) {
                    const float o = __ldg(&obsb[n * DDIM + d]);
                    acc[i] = fma2(dup2(o), wv, acc[i]);
                }
            }
        }
        if (w == 7) {
            const float* sobs = server_obs + (size_t)b * SDIM;
            #pragma unroll
            for (int d = 0; d < SDIM; d++) {
                const float2 wv2 = __ldg((const float2*)&W_srv[d * HID + 2 * lane]);
                const float o = __ldg(&sobs[d]);
                acc[7] = fma2(dup2(o), pk2(wv2.x, wv2.y), acc[7]);
            }
        }
        #pragma unroll
        for (int i = 0; i < 8; i++) {
            float x, y; up2(acc[i], x, y);
            x = fmaxf(x, 0.f) * dinv[i];
            y = fmaxf(y, 0.f) * dinv[i];
            *(float2*)&xb[(w * 8 + i) * PAD + 2 * lane] = make_float2(x, y);
        }
    }
    __syncthreads();

    const float* Ws[3] = {W1, W2, W3};
    const float* bs[3] = {b1, b2, b3};
    // matmul warp tiling: warp covers 4 node-groups x 8 col-groups
    const int ng = (w >> 1) * 4 + (lane >> 3);   // 0..15 -> nodes 4ng..4ng+3
    const int cg = (w & 1) * 8 + (lane & 7);     // 0..15 -> cols  4cg..4cg+3

    // ---------------- Phase 3: three GCN layers
    #pragma unroll
    for (int L = 0; L < 3; L++) {
        // ---- sparse aggregation: xb -> yb (transposed [k][n], scaled by dinv[n])
        {
            const u64* xrow = (const u64*)xb + lane;   // xb[m*PAD + 2*lane]
            #pragma unroll
            for (int i = 0; i < 8; i++) {
                unsigned lo = mlo[i], hi = mhi[i];
                u64 s = 0ULL;
                while (lo) { const int m = __ffs((int)lo) - 1; lo &= lo - 1;
                             s = add2(s, xrow[m * (PAD / 2)]); }
                while (hi) { const int m = __ffs((int)hi) - 1 + 32; hi &= hi - 1;
                             s = add2(s, xrow[m * (PAD / 2)]); }
                s = mul2(s, dup2(dinv[i]));
                float sx, sy; up2(s, sx, sy);
                const int n = w * 8 + i;
                yb[(2 * lane) * PAD + n]     = sx;
                yb[(2 * lane + 1) * PAD + n] = sy;
            }
        }
        __syncthreads();

        // ---- dense matmul: out[n][c] = relu(sum_k y[k][n] * W[k][c] + b[c])
        const float* W = Ws[L];
        u64 acc[4][2];
        {
            const float2 bp0 = __ldg((const float2*)&bs[L][4 * cg]);
            const float2 bp1 = __ldg((const float2*)&bs[L][4 * cg + 2]);
            const u64 b0 = pk2(bp0.x, bp0.y), b1v = pk2(bp1.x, bp1.y);
            #pragma unroll
            for (int j = 0; j < 4; j++) { acc[j][0] = b0; acc[j][1] = b1v; }
        }
        #pragma unroll 4
        for (int k = 0; k < HID; k++) {
            const u64 p01 = *(const u64*)&yb[k * PAD + 4 * ng];
            const u64 p23 = *(const u64*)&yb[k * PAD + 4 * ng + 2];
            float y0, y1, y2, y3;
            up2(p01, y0, y1); up2(p23, y2, y3);
            const u64 d0 = dup2(y0), d1 = dup2(y1), d2 = dup2(y2), d3 = dup2(y3);
            const float4 wv = __ldg((const float4*)&W[k * HID + 4 * cg]);
            const u64 w01 = pk2(wv.x, wv.y), w23 = pk2(wv.z, wv.w);
            acc[0][0] = fma2(d0, w01, acc[0][0]); acc[0][1] = fma2(d0, w23, acc[0][1]);
            acc[1][0] = fma2(d1, w01, acc[1][0]); acc[1][1] = fma2(d1, w23, acc[1][1]);
            acc[2][0] = fma2(d2, w01, acc[2][0]); acc[2][1] = fma2(d2, w23, acc[2][1]);
            acc[3][0] = fma2(d3, w01, acc[3][0]); acc[3][1] = fma2(d3, w23, acc[3][1]);
        }

        if (L < 2) {
            // relu + pre-scale by dinv[n], write node-major xb[n][c]
            #pragma unroll
            for (int j = 0; j < 4; j++) {
                const int n = 4 * ng + j;
                const float dv = dinvS[n];
                #pragma unroll
                for (int cp = 0; cp < 2; cp++) {
                    float x, y; up2(acc[j][cp], x, y);
                    x = fmaxf(x, 0.f) * dv;
                    y = fmaxf(y, 0.f) * dv;
                    *(float2*)&xb[n * PAD + 4 * cg + 2 * cp] = make_float2(x, y);
                }
            }
        } else {
            // layer 3: relu only, write TRANSPOSED h3T[k][n] into xb
            #pragma unroll
            for (int j = 0; j < 4; j++) {
                const int n = 4 * ng + j;
                #pragma unroll
                for (int cp = 0; cp < 2; cp++) {
                    float x, y; up2(acc[j][cp], x, y);
                    xb[(4 * cg + 2 * cp) * PAD + n]     = fmaxf(x, 0.f);
                    xb[(4 * cg + 2 * cp + 1) * PAD + n] = fmaxf(y, 0.f);
                }
            }
        }
        __syncthreads();
    }

    // ---------------- Phase 4: tail = [dev mean | server hidden] from h3T rows
    if (tid < HID) {
        float s = 0.f;
        #pragma unroll 7
        for (int n = 0; n < NDEV; n++) s += xb[tid * PAD + n];
        tailS[tid]       = s * (1.0f / 63.0f);
        tailS[HID + tid] = xb[tid * PAD + NDEV];
    }
    __syncthreads();

    // ---------------- Phase 5a: common[j] = sum_t tail[t]*Wf1[64+t][j] + bf1[j]
    {
        const int jp = tid & 63;      // col pair
        const int ch = tid >> 6;      // chunk 0..3
        u64 c = 0ULL;
        #pragma unroll 8
        for (int tt = 0; tt < 32; tt++) {
            const int t = ch * 32 + tt;
            const float tv = tailS[t];
            const float2 wv = __ldg((const float2*)&Wf1[(HID + t) * HH + 2 * jp]);
            c = fma2(dup2(tv), pk2(wv.x, wv.y), c);
        }
        float cx, cy; up2(c, cx, cy);
        part[ch * HH + 2 * jp]     = cx;
        part[ch * HH + 2 * jp + 1] = cy;
    }
    __syncthreads();
    if (tid < HH) {
        const float c = part[tid] + part[HH + tid] + part[2 * HH + tid]
                      + part[3 * HH + tid] + __ldg(&bf1[tid]);
        comS[tid] = c;
    }
    __syncthreads();

    // ---------------- Phase 5b: head GEMM (per-node part) + final projection
    {
        // tile: 4 nodes (4ng..4ng+3) x 8 cols (8cg..8cg+7)
        const int hcg = cg;   // reuse mapping; cols = 8*hcg .. 8*hcg+7 (hcg 0..15)
        u64 acc[4][4];
        #pragma unroll
        for (int j = 0; j < 4; j++)
            #pragma unroll
            for (int cp = 0; cp < 4; cp++) acc[j][cp] = 0ULL;

        #pragma unroll 4
        for (int k = 0; k < HID; k++) {
            const u64 p01 = *(const u64*)&xb[k * PAD + 4 * ng];
            const u64 p23 = *(const u64*)&xb[k * PAD + 4 * ng + 2];
            float y0, y1, y2, y3;
            up2(p01, y0, y1); up2(p23, y2, y3);
            const u64 d0 = dup2(y0), d1 = dup2(y1), d2 = dup2(y2), d3 = dup2(y3);
            const float4 wa = __ldg((const float4*)&Wf1[k * HH + 8 * hcg]);
            const float4 wb = __ldg((const float4*)&Wf1[k * HH + 8 * hcg + 4]);
            const u64 w0 = pk2(wa.x, wa.y), w1 = pk2(wa.z, wa.w);
            const u64 w2 = pk2(wb.x, wb.y), w3 = pk2(wb.z, wb.w);
            acc[0][0] = fma2(d0, w0, acc[0][0]); acc[0][1] = fma2(d0, w1, acc[0][1]);
            acc[0][2] = fma2(d0, w2, acc[0][2]); acc[0][3] = fma2(d0, w3, acc[0][3]);
            acc[1][0] = fma2(d1, w0, acc[1][0]); acc[1][1] = fma2(d1, w1, acc[1][1]);
            acc[1][2] = fma2(d1, w2, acc[1][2]); acc[1][3] = fma2(d1, w3, acc[1][3]);
            acc[2][0] = fma2(d2, w0, acc[2][0]); acc[2][1] = fma2(d2, w1, acc[2][1]);
            acc[2][2] = fma2(d2, w2, acc[2][2]); acc[2][3] = fma2(d2, w3, acc[2][3]);
            acc[3][0] = fma2(d3, w0, acc[3][0]); acc[3][1] = fma2(d3, w1, acc[3][1]);
            acc[3][2] = fma2(d3, w2, acc[3][2]); acc[3][3] = fma2(d3, w3, acc[3][3]);
        }

        // epilogue: z = relu(acc + common), p = z . Wf2 ; reduce over 8-lane group
        u64 cm[4], wf[4];
        #pragma unroll
        for (int cp = 0; cp < 4; cp++) {
            cm[cp] = *(const u64*)&comS[8 * hcg + 2 * cp];
            const float2 wv = __ldg((const float2*)&Wf2[8 * hcg + 2 * cp]);
            wf[cp] = pk2(wv.x, wv.y);
        }
        float psum[4];
        #pragma unroll
        for (int j = 0; j < 4; j++) {
            u64 pj = 0ULL;
            #pragma unroll
            for (int cp = 0; cp < 4; cp++) {
                const u64 z = add2(acc[j][cp], cm[cp]);
                float zx, zy; up2(z, zx, zy);
                pj = fma2(pk2(fmaxf(zx, 0.f), fmaxf(zy, 0.f)), wf[cp], pj);
            }
            float px, py; up2(pj, px, py);
            float p = px + py;
            p += __shfl_xor_sync(FULL, p, 1);
            p += __shfl_xor_sync(FULL, p, 2);
            p += __shfl_xor_sync(FULL, p, 4);
            psum[j] = p;
        }
        // two warps (w, w^1) hold the two column halves of each node row
        if ((lane & 7) == 0) {
            #pragma unroll
            for (int j = 0; j < 4; j++)
                part[(w & 1) * 64 + 4 * ng + j] = psum[j];
        }
    }
    __syncthreads();

    if (tid < NDEV) {
        out[(size_t)b * NDEV + tid] = part[tid] + part[64 + tid] + __ldg(bf2);
    }
}

extern "C" void kernel_launch(void* const* d_in, const int* in_sizes, int n_in,
                              void* d_out, int out_size)
{
    const float* device_obs = (const float*)d_in[0];
    const float* server_obs = (const float*)d_in[1];
    const float* adjacency  = (const float*)d_in[2];
    const float* W_dev = (const float*)d_in[3];
    const float* b_dev = (const float*)d_in[4];
    const float* W_srv = (const float*)d_in[5];
    const float* b_srv = (const float*)d_in[6];
    const float* W1 = (const float*)d_in[7];
    const float* b1 = (const float*)d_in[8];
    const float* W2 = (const float*)d_in[9];
    const float* b2 = (const float*)d_in[10];
    const float* W3 = (const float*)d_in[11];
    const float* b3 = (const float*)d_in[12];
    const float* Wf1 = (const float*)d_in[13];
    const float* bf1 = (const float*)d_in[14];
    const float* Wf2 = (const float*)d_in[15];
    const float* bf2 = (const float*)d_in[16];

    const int B = in_sizes[1] / SDIM;   // server_obs is (B, 3)

    pgcn_kernel<<<B, 256>>>(device_obs, server_obs, adjacency,
                            W_dev, b_dev, W_srv, b_srv,
                            W1, b1, W2, b2, W3, b3,
                            Wf1, bf1, Wf2, bf2,
                            (float*)d_out);
}

// round 7
// speedup vs baseline: 1.4633x; 1.1469x over previous
#include <cuda_runtime.h>

#define NDEV 63
#define NN   64
#define DDIM 14
#define SDIM 3
#define HID  64
#define HH   128
#define FULL 0xffffffffu
#define PAD  66   // node-major row stride (floats)

// float2-pair layout: row k2 holds feature pair (2k2, 2k2+1) for all 64 nodes.
// ROFF in float2 units; parity term keeps every row 16B-aligned.
#define ROFF(k2)     ((k2) * 65 + ((k2) & 1))
#define YADDR(k2, n) (2 * ROFF(k2) + 2 * (n))      // float index

typedef unsigned long long u64;

__device__ __forceinline__ u64 pk2(float x, float y) {
    u64 r; asm("mov.b64 %0,{%1,%2};" : "=l"(r) : "f"(x), "f"(y)); return r;
}
__device__ __forceinline__ u64 dup2(float x) { return pk2(x, x); }
__device__ __forceinline__ void up2(u64 v, float& x, float& y) {
    asm("mov.b64 {%0,%1},%2;" : "=f"(x), "=f"(y) : "l"(v));
}
__device__ __forceinline__ u64 fma2(u64 a, u64 b, u64 c) {
    u64 d; asm("fma.rn.f32x2 %0,%1,%2,%3;" : "=l"(d) : "l"(a), "l"(b), "l"(c)); return d;
}
__device__ __forceinline__ u64 add2(u64 a, u64 b) {
    u64 d; asm("add.rn.f32x2 %0,%1,%2;" : "=l"(d) : "l"(a), "l"(b)); return d;
}
__device__ __forceinline__ u64 mul2(u64 a, u64 b) {
    u64 d; asm("mul.rn.f32x2 %0,%1,%2;" : "=l"(d) : "l"(a), "l"(b)); return d;
}

__global__ __launch_bounds__(256, 4) void pgcn_kernel(
    const float* __restrict__ device_obs,
    const float* __restrict__ server_obs,
    const float* __restrict__ adjacency,
    const float* __restrict__ W_dev, const float* __restrict__ b_dev,
    const float* __restrict__ W_srv, const float* __restrict__ b_srv,
    const float* __restrict__ W1, const float* __restrict__ b1,
    const float* __restrict__ W2, const float* __restrict__ b2,
    const float* __restrict__ W3, const float* __restrict__ b3,
    const float* __restrict__ Wf1, const float* __restrict__ bf1,
    const float* __restrict__ Wf2, const float* __restrict__ bf2,
    float* __restrict__ out)
{
    __shared__ __align__(16) float xb[NN * PAD];   // node-major [n][h]; reused as h3 pair layout
    __shared__ __align__(16) float yb[4164];       // pair layout [k2][n]
    __shared__ __align__(16) float dinvS[NN];
    __shared__ __align__(16) float tailS[2 * HID]; // [mean | server]
    __shared__ __align__(16) float comS[HH];
    __shared__ __align__(16) float part[4 * HH];

    const int b    = blockIdx.x;
    const int tid  = threadIdx.x;
    const int w    = tid >> 5;
    const int lane = tid & 31;

    // ---------------- Phase 1: adjacency -> warp-uniform bitmasks + dinv
    unsigned mlo[8], mhi[8];
    float dinv[8];
    {
        const float* adj = adjacency + (size_t)b * NN * NN;
        #pragma unroll
        for (int i = 0; i < 8; i++) {
            const int n = w * 8 + i;
            const float a0 = adj[n * 64 + lane];
            const float a1 = adj[n * 64 + 32 + lane];
            mlo[i] = __ballot_sync(FULL, a0 > 0.5f);
            mhi[i] = __ballot_sync(FULL, a1 > 0.5f);
            const int deg = __popc(mlo[i]) + __popc(mhi[i]);  // >= 1 (self loop)
            dinv[i] = rsqrtf((float)deg);
            if (lane == 0) dinvS[n] = dinv[i];
        }
    }

    // ---------------- Phase 2: embeddings -> xb[n][h] (relu, pre-scaled by dinv)
    {
        // coalesced obs load: this warp's 8 nodes = 112 floats (warp 7: 98)
        float rr[4];
        {
            const float* base = device_obs + ((size_t)b * NDEV + w * 8) * DDIM;
            const int lim = (w < 7) ? 112 : 98;
            #pragma unroll
            for (int t = 0; t < 4; t++) {
                const int idx = lane + 32 * t;
                rr[t] = (idx < lim) ? __ldg(&base[idx]) : 0.f;
            }
        }
        u64 acc[8];
        {
            const float2 bdv = __ldg((const float2*)&b_dev[2 * lane]);
            const u64 bd = pk2(bdv.x, bdv.y);
            #pragma unroll
            for (int i = 0; i < 8; i++) acc[i] = bd;
        }
        #pragma unroll
        for (int d = 0; d < DDIM; d++) {
            const float2 wv2 = __ldg((const float2*)&W_dev[d * HID + 2 * lane]);
            const u64 wv = pk2(wv2.x, wv2.y);
            #pragma unroll
            for (int i = 0; i < 8; i++) {
                const int idx = i * DDIM + d;            // compile-time constant
                const float o = __shfl_sync(FULL, rr[idx >> 5], idx & 31);
                acc[i] = fma2(dup2(o), wv, acc[i]);
            }
        }
        if (w == 7) {   // node 63 = server: recompute acc[7] from scratch
            const float2 bsv = __ldg((const float2*)&b_srv[2 * lane]);
            u64 a7 = pk2(bsv.x, bsv.y);
            const float* sobs = server_obs + (size_t)b * SDIM;
            #pragma unroll
            for (int d = 0; d < SDIM; d++) {
                const float2 wv2 = __ldg((const float2*)&W_srv[d * HID + 2 * lane]);
                a7 = fma2(dup2(__ldg(&sobs[d])), pk2(wv2.x, wv2.y), a7);
            }
            acc[7] = a7;
        }
        #pragma unroll
        for (int i = 0; i < 8; i++) {
            float x, y; up2(acc[i], x, y);
            x = fmaxf(x, 0.f) * dinv[i];
            y = fmaxf(y, 0.f) * dinv[i];
            *(float2*)&xb[(w * 8 + i) * PAD + 2 * lane] = make_float2(x, y);
        }
    }
    __syncthreads();

    const float* Ws[3] = {W1, W2, W3};
    const float* bs[3] = {b1, b2, b3};
    const int ng = (w >> 1) * 4 + (lane >> 3);   // 16 node-groups: nodes 4ng..4ng+3
    const int cg = (w & 1) * 8 + (lane & 7);     // 16 col-groups:  cols  4cg..4cg+3
    float* const h3 = xb;                        // layer-3 output, pair layout

    // ---------------- Phase 3: three GCN layers
    #pragma unroll
    for (int L = 0; L < 3; L++) {
        // ---- sparse aggregation: xb (node-major) -> yb (pair layout), *dinv[n]
        {
            const u64* xrow = (const u64*)xb + lane;   // xb[m*PAD + 2*lane]
            #pragma unroll
            for (int i = 0; i < 8; i++) {
                unsigned lo = mlo[i], hi = mhi[i];
                u64 s = 0ULL;
                while (lo) { const int m = __ffs((int)lo) - 1; lo &= lo - 1;
                             s = add2(s, xrow[m * (PAD / 2)]); }
                while (hi) { const int m = __ffs((int)hi) - 1 + 32; hi &= hi - 1;
                             s = add2(s, xrow[m * (PAD / 2)]); }
                s = mul2(s, dup2(dinv[i]));
                float sx, sy; up2(s, sx, sy);
                *(float2*)&yb[YADDR(lane, w * 8 + i)] = make_float2(sx, sy);
            }
        }
        __syncthreads();

        // ---- dense matmul: out[n][c] = relu(sum_k y[k][n] * W[k][c] + b[c])
        const float* W = Ws[L];
        u64 acc[4][2];
        {
            const float2 bp0 = __ldg((const float2*)&bs[L][4 * cg]);
            const float2 bp1 = __ldg((const float2*)&bs[L][4 * cg + 2]);
            const u64 b0 = pk2(bp0.x, bp0.y), b1v = pk2(bp1.x, bp1.y);
            #pragma unroll
            for (int j = 0; j < 4; j++) { acc[j][0] = b0; acc[j][1] = b1v; }
        }
        #pragma unroll 4
        for (int k2 = 0; k2 < 32; k2++) {
            // qa = (f0@n0, f1@n0, f0@n1, f1@n1) with f0=2k2, f1=2k2+1
            const float4 qa = *(const float4*)&yb[YADDR(k2, 4 * ng)];
            const float4 qb = *(const float4*)&yb[YADDR(k2, 4 * ng + 2)];
            const float4 w0 = __ldg((const float4*)&W[(2 * k2)     * HID + 4 * cg]);
            const float4 w1 = __ldg((const float4*)&W[(2 * k2 + 1) * HID + 4 * cg]);
            const u64 w0a = pk2(w0.x, w0.y), w0b = pk2(w0.z, w0.w);
            const u64 w1a = pk2(w1.x, w1.y), w1b = pk2(w1.z, w1.w);
            acc[0][0] = fma2(dup2(qa.x), w0a, acc[0][0]); acc[0][1] = fma2(dup2(qa.x), w0b, acc[0][1]);
            acc[0][0] = fma2(dup2(qa.y), w1a, acc[0][0]); acc[0][1] = fma2(dup2(qa.y), w1b, acc[0][1]);
            acc[1][0] = fma2(dup2(qa.z), w0a, acc[1][0]); acc[1][1] = fma2(dup2(qa.z), w0b, acc[1][1]);
            acc[1][0] = fma2(dup2(qa.w), w1a, acc[1][0]); acc[1][1] = fma2(dup2(qa.w), w1b, acc[1][1]);
            acc[2][0] = fma2(dup2(qb.x), w0a, acc[2][0]); acc[2][1] = fma2(dup2(qb.x), w0b, acc[2][1]);
            acc[2][0] = fma2(dup2(qb.y), w1a, acc[2][0]); acc[2][1] = fma2(dup2(qb.y), w1b, acc[2][1]);
            acc[3][0] = fma2(dup2(qb.z), w0a, acc[3][0]); acc[3][1] = fma2(dup2(qb.z), w0b, acc[3][1]);
            acc[3][0] = fma2(dup2(qb.w), w1a, acc[3][0]); acc[3][1] = fma2(dup2(qb.w), w1b, acc[3][1]);
        }

        if (L < 2) {
            #pragma unroll
            for (int j = 0; j < 4; j++) {
                const int n = 4 * ng + j;
                const float dv = dinvS[n];
                #pragma unroll
                for (int cp = 0; cp < 2; cp++) {
                    float x, y; up2(acc[j][cp], x, y);
                    x = fmaxf(x, 0.f) * dv;
                    y = fmaxf(y, 0.f) * dv;
                    *(float2*)&xb[n * PAD + 4 * cg + 2 * cp] = make_float2(x, y);
                }
            }
        } else {
            // layer 3: relu, store into pair layout h3[k2][n] (k2 = 2cg+cp)
            #pragma unroll
            for (int j = 0; j < 4; j++) {
                const int n = 4 * ng + j;
                #pragma unroll
                for (int cp = 0; cp < 2; cp++) {
                    float x, y; up2(acc[j][cp], x, y);
                    *(float2*)&h3[YADDR(2 * cg + cp, n)] =
                        make_float2(fmaxf(x, 0.f), fmaxf(y, 0.f));
                }
            }
        }
        __syncthreads();
    }

    // ---------------- Phase 4: tail = [dev mean | server hidden], parallel
    {
        const int f  = tid & 63;            // feature index
        const int qq = tid >> 6;            // node chunk 0..3 (warp-uniform)
        const int k2 = f >> 1, comp = f & 1;
        const int nbase = qq * 16;
        const int cnt = (qq < 3) ? 16 : 15; // exclude node 63
        float s = 0.f;
        #pragma unroll
        for (int n = 0; n < 16; n++)
            if (n < cnt) s += h3[YADDR(k2, nbase + n) + comp];
        part[qq * 64 + f] = s;
    }
    __syncthreads();
    if (tid < HID) {
        const int k2 = tid >> 1, comp = tid & 1;
        tailS[tid] = (part[tid] + part[64 + tid] + part[128 + tid] + part[192 + tid])
                     * (1.0f / 63.0f);
        tailS[HID + tid] = h3[YADDR(k2, 63) + comp];
    }
    __syncthreads();

    // ---------------- Phase 5a: common[j] = sum_t tail[t]*Wf1[64+t][j] + bf1[j]
    {
        const int jp = tid & 63;
        const int ch = tid >> 6;
        u64 c = 0ULL;
        #pragma unroll 8
        for (int tt = 0; tt < 32; tt++) {
            const int t = ch * 32 + tt;
            const float tv = tailS[t];
            const float2 wv = __ldg((const float2*)&Wf1[(HID + t) * HH + 2 * jp]);
            c = fma2(dup2(tv), pk2(wv.x, wv.y), c);
        }
        float cx, cy; up2(c, cx, cy);
        part[ch * HH + 2 * jp]     = cx;
        part[ch * HH + 2 * jp + 1] = cy;
    }
    __syncthreads();
    if (tid < HH) {
        comS[tid] = part[tid] + part[HH + tid] + part[2 * HH + tid]
                  + part[3 * HH + tid] + __ldg(&bf1[tid]);
    }
    __syncthreads();

    // ---------------- Phase 5b: head GEMM (per-node part) + final projection
    {
        const int cb = 64 * (w & 1);        // warp's column half of 128
        const int q  = lane & 7;            // cols cb+4q..+3 and cb+32+4q..+3
        u64 acc[4][4];
        #pragma unroll
        for (int j = 0; j < 4; j++)
            #pragma unroll
            for (int cp = 0; cp < 4; cp++) acc[j][cp] = 0ULL;

        #pragma unroll 4
        for (int k2 = 0; k2 < 32; k2++) {
            const float4 qa = *(const float4*)&h3[YADDR(k2, 4 * ng)];
            const float4 qb = *(const float4*)&h3[YADDR(k2, 4 * ng + 2)];
            const float4 wa0 = __ldg((const float4*)&Wf1[(2 * k2)     * HH + cb + 4 * q]);
            const float4 wa1 = __ldg((const float4*)&Wf1[(2 * k2)     * HH + cb + 32 + 4 * q]);
            const float4 wb0 = __ldg((const float4*)&Wf1[(2 * k2 + 1) * HH + cb + 4 * q]);
            const float4 wb1 = __ldg((const float4*)&Wf1[(2 * k2 + 1) * HH + cb + 32 + 4 * q]);
            const u64 u0 = pk2(wa0.x, wa0.y), u1 = pk2(wa0.z, wa0.w);
            const u64 u2 = pk2(wa1.x, wa1.y), u3 = pk2(wa1.z, wa1.w);
            const u64 v0 = pk2(wb0.x, wb0.y), v1 = pk2(wb0.z, wb0.w);
            const u64 v2 = pk2(wb1.x, wb1.y), v3 = pk2(wb1.z, wb1.w);
            {
                const u64 d0 = dup2(qa.x), d1 = dup2(qa.y);
                acc[0][0] = fma2(d0, u0, acc[0][0]); acc[0][1] = fma2(d0, u1, acc[0][1]);
                acc[0][2] = fma2(d0, u2, acc[0][2]); acc[0][3] = fma2(d0, u3, acc[0][3]);
                acc[0][0] = fma2(d1, v0, acc[0][0]); acc[0][1] = fma2(d1, v1, acc[0][1]);
                acc[0][2] = fma2(d1, v2, acc[0][2]); acc[0][3] = fma2(d1, v3, acc[0][3]);
            }
            {
                const u64 d0 = dup2(qa.z), d1 = dup2(qa.w);
                acc[1][0] = fma2(d0, u0, acc[1][0]); acc[1][1] = fma2(d0, u1, acc[1][1]);
                acc[1][2] = fma2(d0, u2, acc[1][2]); acc[1][3] = fma2(d0, u3, acc[1][3]);
                acc[1][0] = fma2(d1, v0, acc[1][0]); acc[1][1] = fma2(d1, v1, acc[1][1]);
                acc[1][2] = fma2(d1, v2, acc[1][2]); acc[1][3] = fma2(d1, v3, acc[1][3]);
            }
            {
                const u64 d0 = dup2(qb.x), d1 = dup2(qb.y);
                acc[2][0] = fma2(d0, u0, acc[2][0]); acc[2][1] = fma2(d0, u1, acc[2][1]);
                acc[2][2] = fma2(d0, u2, acc[2][2]); acc[2][3] = fma2(d0, u3, acc[2][3]);
                acc[2][0] = fma2(d1, v0, acc[2][0]); acc[2][1] = fma2(d1, v1, acc[2][1]);
                acc[2][2] = fma2(d1, v2, acc[2][2]); acc[2][3] = fma2(d1, v3, acc[2][3]);
            }
            {
                const u64 d0 = dup2(qb.z), d1 = dup2(qb.w);
                acc[3][0] = fma2(d0, u0, acc[3][0]); acc[3][1] = fma2(d0, u1, acc[3][1]);
                acc[3][2] = fma2(d0, u2, acc[3][2]); acc[3][3] = fma2(d0, u3, acc[3][3]);
                acc[3][0] = fma2(d1, v0, acc[3][0]); acc[3][1] = fma2(d1, v1, acc[3][1]);
                acc[3][2] = fma2(d1, v2, acc[3][2]); acc[3][3] = fma2(d1, v3, acc[3][3]);
            }
        }

        // epilogue: z = relu(acc + common), p = z . Wf2 ; reduce over 8-lane group
        u64 cm[4], wf[4];
        cm[0] = *(const u64*)&comS[cb + 4 * q];
        cm[1] = *(const u64*)&comS[cb + 4 * q + 2];
        cm[2] = *(const u64*)&comS[cb + 32 + 4 * q];
        cm[3] = *(const u64*)&comS[cb + 32 + 4 * q + 2];
        {
            const float2 a0 = __ldg((const float2*)&Wf2[cb + 4 * q]);
            const float2 a1 = __ldg((const float2*)&Wf2[cb + 4 * q + 2]);
            const float2 a2 = __ldg((const float2*)&Wf2[cb + 32 + 4 * q]);
            const float2 a3 = __ldg((const float2*)&Wf2[cb + 32 + 4 * q + 2]);
            wf[0] = pk2(a0.x, a0.y); wf[1] = pk2(a1.x, a1.y);
            wf[2] = pk2(a2.x, a2.y); wf[3] = pk2(a3.x, a3.y);
        }
        float psum[4];
        #pragma unroll
        for (int j = 0; j < 4; j++) {
            u64 pj = 0ULL;
            #pragma unroll
            for (int cp = 0; cp < 4; cp++) {
                const u64 z = add2(acc[j][cp], cm[cp]);
                float zx, zy; up2(z, zx, zy);
                pj = fma2(pk2(fmaxf(zx, 0.f), fmaxf(zy, 0.f)), wf[cp], pj);
            }
            float px, py; up2(pj, px, py);
            float p = px + py;
            p += __shfl_xor_sync(FULL, p, 1);
            p += __shfl_xor_sync(FULL, p, 2);
            p += __shfl_xor_sync(FULL, p, 4);
            psum[j] = p;
        }
        if ((lane & 7) == 0) {
            #pragma unroll
            for (int j = 0; j < 4; j++)
                part[(w & 1) * 64 + 4 * ng + j] = psum[j];
        }
    }
    __syncthreads();

    if (tid < NDEV) {
        out[(size_t)b * NDEV + tid] = part[tid] + part[64 + tid] + __ldg(bf2);
    }
}

extern "C" void kernel_launch(void* const* d_in, const int* in_sizes, int n_in,
                              void* d_out, int out_size)
{
    const float* device_obs = (const float*)d_in[0];
    const float* server_obs = (const float*)d_in[1];
    const float* adjacency  = (const float*)d_in[2];
    const float* W_dev = (const float*)d_in[3];
    const float* b_dev = (const float*)d_in[4];
    const float* W_srv = (const float*)d_in[5];
    const float* b_srv = (const float*)d_in[6];
    const float* W1 = (const float*)d_in[7];
    const float* b1 = (const float*)d_in[8];
    const float* W2 = (const float*)d_in[9];
    const float* b2 = (const float*)d_in[10];
    const float* W3 = (const float*)d_in[11];
    const float* b3 = (const float*)d_in[12];
    const float* Wf1 = (const float*)d_in[13];
    const float* bf1 = (const float*)d_in[14];
    const float* Wf2 = (const float*)d_in[15];
    const float* bf2 = (const float*)d_in[16];

    const int B = in_sizes[1] / SDIM;   // server_obs is (B, 3)

    pgcn_kernel<<<B, 256>>>(device_obs, server_obs, adjacency,
                            W_dev, b_dev, W_srv, b_srv,
                            W1, b1, W2, b2, W3, b3,
                            Wf1, bf1, Wf2, bf2,
                            (float*)d_out);
}